// round 1
// baseline (speedup 1.0000x reference)
#include <cuda_runtime.h>

#define BB 200000      // batch size
#define NN 400000      // nodes = 2*BB
#define DD 128         // embedding dim

// Scratch (device-global: no allocations allowed in kernel_launch)
__device__ float g_deg[NN];                  // degree -> dinv (in place)
__device__ float g_H [(size_t)NN * DD];      // h = x @ W
__device__ float g_P0[(size_t)NN * DD];      // ping (agg / x)
__device__ float g_P1[(size_t)NN * DD];      // pong (agg / x)

__device__ __forceinline__ void red_add4(float* p, float4 v) {
    asm volatile("red.global.add.v4.f32 [%0], {%1,%2,%3,%4};"
                 :: "l"(p), "f"(v.x), "f"(v.y), "f"(v.z), "f"(v.w) : "memory");
}

__global__ void init_deg_kernel() {
    int i = blockIdx.x * blockDim.x + threadIdx.x;
    if (i < NN) g_deg[i] = 1.0f;   // self-loop
}

__global__ void count_deg_kernel(const int* __restrict__ ui, const int* __restrict__ ii) {
    int e = blockIdx.x * blockDim.x + threadIdx.x;
    if (e < BB) {
        atomicAdd(&g_deg[ii[e]], 1.0f);        // dst of edge (user->item)
        atomicAdd(&g_deg[ui[e] + BB], 1.0f);   // dst of edge (item->user)
    }
}

__global__ void dinv_kernel() {
    int i = blockIdx.x * blockDim.x + threadIdx.x;
    if (i < NN) g_deg[i] = 1.0f / sqrtf(g_deg[i]);
}

// x0[i] = user_table[ui[i]] (i<B) else item_table[ii[i-B]]
__global__ void gather_kernel(const int* __restrict__ ui, const int* __restrict__ ii,
                              const float* __restrict__ UT, const float* __restrict__ IT,
                              float* __restrict__ X) {
    int idx = blockIdx.x * blockDim.x + threadIdx.x;   // over NN*32 float4
    if (idx >= NN * 32) return;
    int row = idx >> 5, c = idx & 31;
    int src; const float4* T;
    if (row < BB) { src = ui[row];      T = (const float4*)UT; }
    else          { src = ii[row - BB]; T = (const float4*)IT; }
    ((float4*)X)[idx] = T[src * 32 + c];
}

// H = act(X) @ W ; AGG = dinv^2 * H (self-loop init)
// act = identity (has_act=0) or relu(x + bprev) (has_act=1)
// Tile: 64 rows per block, full K=N=128. W in smem. Warp owns 8 rows x (lane*4) cols.
__global__ void __launch_bounds__(256, 2)
gemm_kernel(const float* __restrict__ X, const float* __restrict__ W,
            const float* __restrict__ bprev, int has_act,
            const float* __restrict__ dinv,
            float* __restrict__ H, float* __restrict__ AGG)
{
    extern __shared__ float sm[];
    float* Wsm = sm;                 // 128*128
    float* Asm = sm + DD * DD;       // 64*128
    float* bsm = Asm + 64 * DD;      // 128

    int tid = threadIdx.x;

    const float4* Wg = (const float4*)W;
    float4* Ws4 = (float4*)Wsm;
#pragma unroll
    for (int i = 0; i < 16; i++) Ws4[tid + i * 256] = Wg[tid + i * 256];
    if (tid < DD) bsm[tid] = has_act ? bprev[tid] : 0.0f;
    __syncthreads();

    size_t row0 = (size_t)blockIdx.x * 64;
    const float4* Ag = (const float4*)(X + row0 * DD);
    float4* As4 = (float4*)Asm;
#pragma unroll
    for (int i = 0; i < 8; i++) {
        int idx = tid + i * 256;
        float4 v = Ag[idx];
        if (has_act) {
            int c = (idx & 31) * 4;
            v.x = fmaxf(v.x + bsm[c + 0], 0.0f);
            v.y = fmaxf(v.y + bsm[c + 1], 0.0f);
            v.z = fmaxf(v.z + bsm[c + 2], 0.0f);
            v.w = fmaxf(v.w + bsm[c + 3], 0.0f);
        }
        As4[idx] = v;
    }
    __syncthreads();

    int warp = tid >> 5, lane = tid & 31;
    const float* Ab = Asm + warp * 8 * DD;
    float acc[8][4];
#pragma unroll
    for (int i = 0; i < 8; i++) { acc[i][0] = 0.f; acc[i][1] = 0.f; acc[i][2] = 0.f; acc[i][3] = 0.f; }

#pragma unroll 8
    for (int k = 0; k < DD; k++) {
        float4 b = ((const float4*)(Wsm + k * DD))[lane];
#pragma unroll
        for (int i = 0; i < 8; i++) {
            float a = Ab[i * DD + k];
            acc[i][0] += a * b.x; acc[i][1] += a * b.y;
            acc[i][2] += a * b.z; acc[i][3] += a * b.w;
        }
    }

#pragma unroll
    for (int i = 0; i < 8; i++) {
        size_t r = row0 + (size_t)(warp * 8 + i);
        float dv = dinv[r]; float d2 = dv * dv;
        float4 h = make_float4(acc[i][0], acc[i][1], acc[i][2], acc[i][3]);
        ((float4*)(H + r * DD))[lane] = h;
        ((float4*)(AGG + r * DD))[lane] = make_float4(h.x * d2, h.y * d2, h.z * d2, h.w * d2);
    }
}

// One warp per batch element; both edge directions; vector reduction into AGG.
__global__ void scatter_kernel(const int* __restrict__ ui, const int* __restrict__ ii,
                               const float* __restrict__ H, const float* __restrict__ dinv,
                               float* __restrict__ AGG) {
    int t = blockIdx.x * blockDim.x + threadIdx.x;
    int e = t >> 5;
    if (e >= BB) return;
    int lane = t & 31;
    int a = ii[e];          // item-index node id
    int b = ui[e] + BB;     // user-index node id (+n/2)
    float norm = dinv[a] * dinv[b];
    float4 va = ((const float4*)(H + (size_t)b * DD))[lane];  // msg into a from b
    float4 vb = ((const float4*)(H + (size_t)a * DD))[lane];  // msg into b from a
    va.x *= norm; va.y *= norm; va.z *= norm; va.w *= norm;
    vb.x *= norm; vb.y *= norm; vb.z *= norm; vb.w *= norm;
    red_add4(AGG + (size_t)a * DD + lane * 4, va);
    red_add4(AGG + (size_t)b * DD + lane * 4, vb);
}

__global__ void final_kernel(const float* __restrict__ Z, const float* __restrict__ b,
                             float* __restrict__ out) {
    int idx = blockIdx.x * blockDim.x + threadIdx.x;   // over NN*32 float4
    if (idx >= NN * 32) return;
    int c = idx & 31;
    float4 v = ((const float4*)Z)[idx];
    float4 bb = ((const float4*)b)[c];
    v.x = fmaxf(v.x + bb.x, 0.0f);
    v.y = fmaxf(v.y + bb.y, 0.0f);
    v.z = fmaxf(v.z + bb.z, 0.0f);
    v.w = fmaxf(v.w + bb.w, 0.0f);
    ((float4*)out)[idx] = v;
}

extern "C" void kernel_launch(void* const* d_in, const int* in_sizes, int n_in,
                              void* d_out, int out_size) {
    const int*   ui   = (const int*)d_in[0];
    const int*   ii   = (const int*)d_in[1];
    const float* UT   = (const float*)d_in[2];
    const float* IT   = (const float*)d_in[3];
    const float* Wall = (const float*)d_in[4];   // [3,128,128]
    const float* ball = (const float*)d_in[5];   // [3,128]
    float* out = (float*)d_out;

    float *deg, *H, *P0, *P1;
    cudaGetSymbolAddress((void**)&deg, g_deg);
    cudaGetSymbolAddress((void**)&H,   g_H);
    cudaGetSymbolAddress((void**)&P0,  g_P0);
    cudaGetSymbolAddress((void**)&P1,  g_P1);

    int smem = (DD * DD + 64 * DD + DD) * (int)sizeof(float);   // ~98.8 KB
    cudaFuncSetAttribute(gemm_kernel, cudaFuncAttributeMaxDynamicSharedMemorySize, smem);

    init_deg_kernel<<<(NN + 255) / 256, 256>>>();
    count_deg_kernel<<<(BB + 255) / 256, 256>>>(ui, ii);
    dinv_kernel<<<(NN + 255) / 256, 256>>>();               // g_deg now holds dinv
    gather_kernel<<<(NN * 32 + 255) / 256, 256>>>(ui, ii, UT, IT, P1);

    // layer 0: x0 in P1 (no act)
    gemm_kernel<<<NN / 64, 256, smem>>>(P1, Wall, nullptr, 0, deg, H, P0);
    scatter_kernel<<<(BB * 32 + 255) / 256, 256>>>(ui, ii, H, deg, P0);
    // layer 1: relu(P0 + b0)
    gemm_kernel<<<NN / 64, 256, smem>>>(P0, Wall + DD * DD, ball, 1, deg, H, P1);
    scatter_kernel<<<(BB * 32 + 255) / 256, 256>>>(ui, ii, H, deg, P1);
    // layer 2: relu(P1 + b1)
    gemm_kernel<<<NN / 64, 256, smem>>>(P1, Wall + 2 * DD * DD, ball + DD, 1, deg, H, P0);
    scatter_kernel<<<(BB * 32 + 255) / 256, 256>>>(ui, ii, H, deg, P0);

    final_kernel<<<(NN * 32 + 255) / 256, 256>>>(P0, ball + 2 * DD, out);
}

// round 3
// speedup vs baseline: 1.3631x; 1.3631x over previous
#include <cuda_runtime.h>
#include <cuda_bf16.h>
#include <cstdint>

#define BB 200000      // batch size
#define NN 400000      // nodes = 2*BB
#define DD 128         // embedding dim
#define PITCH 136      // padded bf16 pitch for smem tiles (272B rows)

// ---------------- scratch (device globals; no allocs allowed) ----------------
__device__ float g_deg[NN];                       // degree -> dinv (in place)
__device__ float g_H [(size_t)NN * DD];           // h = x @ W
__device__ float g_P0[(size_t)NN * DD];           // ping (agg buffer)
__device__ float g_P1[(size_t)NN * DD];           // pong (agg buffer)
__device__ __align__(16) char g_Wt_hi[3][128 * PITCH * 2];  // W^T bf16 hi, padded n-major
__device__ __align__(16) char g_Wt_lo[3][128 * PITCH * 2];  // W^T bf16 lo

// ---------------- helpers ----------------
__device__ __forceinline__ uint32_t smem_u32(const void* p) {
    uint32_t a;
    asm("{ .reg .u64 t; cvta.to.shared.u64 t, %1; cvt.u32.u64 %0, t; }" : "=r"(a) : "l"(p));
    return a;
}
__device__ __forceinline__ void red_add4(float* p, float4 v) {
    asm volatile("red.global.add.v4.f32 [%0], {%1,%2,%3,%4};"
                 :: "l"(p), "f"(v.x), "f"(v.y), "f"(v.z), "f"(v.w) : "memory");
}
__device__ __forceinline__ void ldm_x4(uint32_t a, uint32_t& r0, uint32_t& r1,
                                       uint32_t& r2, uint32_t& r3) {
    asm volatile("ldmatrix.sync.aligned.m8n8.x4.shared.b16 {%0,%1,%2,%3}, [%4];"
                 : "=r"(r0), "=r"(r1), "=r"(r2), "=r"(r3) : "r"(a));
}
__device__ __forceinline__ void mma_bf16(float* c, const uint32_t* a, uint32_t b0, uint32_t b1) {
    asm volatile("mma.sync.aligned.m16n8k16.row.col.f32.bf16.bf16.f32 "
                 "{%0,%1,%2,%3}, {%4,%5,%6,%7}, {%8,%9}, {%0,%1,%2,%3};"
                 : "+f"(c[0]), "+f"(c[1]), "+f"(c[2]), "+f"(c[3])
                 : "r"(a[0]), "r"(a[1]), "r"(a[2]), "r"(a[3]), "r"(b0), "r"(b1));
}

// ---------------- trivial kernels ----------------
__global__ void init_deg_kernel() {
    int i = blockIdx.x * blockDim.x + threadIdx.x;
    if (i < NN) g_deg[i] = 1.0f;
}
__global__ void count_deg_kernel(const int* __restrict__ ui, const int* __restrict__ ii) {
    int e = blockIdx.x * blockDim.x + threadIdx.x;
    if (e < BB) {
        atomicAdd(&g_deg[ii[e]], 1.0f);
        atomicAdd(&g_deg[ui[e] + BB], 1.0f);
    }
}
__global__ void dinv_kernel() {
    int i = blockIdx.x * blockDim.x + threadIdx.x;
    if (i < NN) g_deg[i] = 1.0f / sqrtf(g_deg[i]);
}

// W^T (Wt[n][k] = W[k][n]) -> bf16 hi/lo, padded pitch
__global__ void wprep_kernel(const float* __restrict__ Wall) {
    int idx = blockIdx.x * blockDim.x + threadIdx.x;   // 3*128*128
    if (idx >= 3 * 128 * 128) return;
    int l = idx / 16384, r = idx % 16384;
    int k = r / 128, n = r % 128;
    float v = Wall[l * 16384 + k * 128 + n];
    __nv_bfloat16 hi = __float2bfloat16(v);
    __nv_bfloat16 lo = __float2bfloat16(v - __bfloat162float(hi));
    uint32_t off = ((uint32_t)n * PITCH + (uint32_t)k) * 2;
    *(__nv_bfloat16*)(g_Wt_hi[l] + off) = hi;
    *(__nv_bfloat16*)(g_Wt_lo[l] + off) = lo;
}

// ---------------- HMMA GEMM ----------------
// H = act(X) @ W ; AGG = dinv^2 * H.  128-row tile/CTA, 256 threads (8 warps).
// If gather0: A rows come straight from the embedding tables (fused gather).
#define SM_AHI  0
#define SM_ALO  (128 * PITCH * 2)          // 34816
#define SM_WHI  (2 * 128 * PITCH * 2)      // 69632
#define SM_WLO  (3 * 128 * PITCH * 2)      // 104448
#define SM_BIAS (4 * 128 * PITCH * 2)      // 139264
#define SM_TOTAL (SM_BIAS + 512)

__global__ void __launch_bounds__(256, 1)
tc_gemm_kernel(const float* __restrict__ X,
               const int* __restrict__ ui, const int* __restrict__ ii, int gather0,
               int layer, const float* __restrict__ bprev, int has_act,
               const float* __restrict__ dinv,
               float* __restrict__ H, float* __restrict__ AGG)
{
    extern __shared__ char smem[];
    uint32_t sb = smem_u32(smem);
    int tid = threadIdx.x, warp = tid >> 5, lane = tid & 31;
    size_t row0 = (size_t)blockIdx.x * 128;

    // copy padded W tiles (34816B each = 2176 uint4)
    {
        const uint4* wh = (const uint4*)g_Wt_hi[layer];
        const uint4* wl = (const uint4*)g_Wt_lo[layer];
        uint4* dh = (uint4*)(smem + SM_WHI);
        uint4* dl = (uint4*)(smem + SM_WLO);
#pragma unroll
        for (int i = 0; i < 8; i++) { dh[tid + i * 256] = wh[tid + i * 256];
                                      dl[tid + i * 256] = wl[tid + i * 256]; }
        if (tid < 128) { dh[2048 + tid] = wh[2048 + tid]; dl[2048 + tid] = wl[2048 + tid]; }
    }
    if (tid < 128) ((float*)(smem + SM_BIAS))[tid] = has_act ? bprev[tid] : 0.0f;
    __syncthreads();
    const float* bsm = (const float*)(smem + SM_BIAS);

    // A tile: load, act, bf16 hi/lo split, store padded
#pragma unroll
    for (int i = 0; i < 16; i++) {
        int row = warp * 16 + i;
        size_t grow = row0 + row;
        const float4* src;
        if (gather0) {
            if (grow < BB) src = (const float4*)(X + (size_t)ui[grow] * DD);          // user table
            else           src = (const float4*)(((const float*)ii) + 0),              // placeholder
                           src = (const float4*)(bprev + 0);                           // (unused path)
        }
        float4 v;
        if (gather0) {
            // X = user_table, bprev = item_table in gather mode (reuse params)
            const float* UT = X;
            const float* IT = (const float*)dinv - 0;  // never used; see below
            (void)IT;
            if (grow < BB) v = ((const float4*)(UT + (size_t)ui[grow] * DD))[lane];
            else           v = ((const float4*)(((const float*)bprev) + (size_t)ii[grow - BB] * DD))[lane];
        } else {
            v = ((const float4*)(X + grow * DD))[lane];
        }
        if (has_act) {
            int c = lane * 4;
            v.x = fmaxf(v.x + bsm[c + 0], 0.0f);
            v.y = fmaxf(v.y + bsm[c + 1], 0.0f);
            v.z = fmaxf(v.z + bsm[c + 2], 0.0f);
            v.w = fmaxf(v.w + bsm[c + 3], 0.0f);
        }
        __nv_bfloat16 h0 = __float2bfloat16(v.x), h1 = __float2bfloat16(v.y);
        __nv_bfloat16 h2 = __float2bfloat16(v.z), h3 = __float2bfloat16(v.w);
        __nv_bfloat16 l0 = __float2bfloat16(v.x - __bfloat162float(h0));
        __nv_bfloat16 l1 = __float2bfloat16(v.y - __bfloat162float(h1));
        __nv_bfloat16 l2 = __float2bfloat16(v.z - __bfloat162float(h2));
        __nv_bfloat16 l3 = __float2bfloat16(v.w - __bfloat162float(h3));
        uint2 hp, lp;
        hp.x = (uint32_t)__bfloat16_as_ushort(h0) | ((uint32_t)__bfloat16_as_ushort(h1) << 16);
        hp.y = (uint32_t)__bfloat16_as_ushort(h2) | ((uint32_t)__bfloat16_as_ushort(h3) << 16);
        lp.x = (uint32_t)__bfloat16_as_ushort(l0) | ((uint32_t)__bfloat16_as_ushort(l1) << 16);
        lp.y = (uint32_t)__bfloat16_as_ushort(l2) | ((uint32_t)__bfloat16_as_ushort(l3) << 16);
        uint32_t off = ((uint32_t)row * PITCH + (uint32_t)lane * 4) * 2;
        *(uint2*)(smem + SM_AHI + off) = hp;
        *(uint2*)(smem + SM_ALO + off) = lp;
    }
    __syncthreads();

    // ldmatrix lane addressing
    int arow = warp * 16 + (lane & 15);
    uint32_t aoff = sb + SM_AHI + ((uint32_t)arow * PITCH + (uint32_t)((lane >> 4) * 8)) * 2;
    int brow = (lane & 7) + ((lane >> 4) & 1) * 8;
    uint32_t boff = sb + SM_WHI + ((uint32_t)brow * PITCH + (uint32_t)(((lane >> 3) & 1) * 8)) * 2;

    float acc[16][4];
#pragma unroll
    for (int i = 0; i < 16; i++) { acc[i][0] = acc[i][1] = acc[i][2] = acc[i][3] = 0.f; }

#pragma unroll
    for (int k = 0; k < 8; k++) {
        uint32_t ah[4], al[4];
        uint32_t ak = aoff + (uint32_t)k * 32;
        ldm_x4(ak, ah[0], ah[1], ah[2], ah[3]);
        ldm_x4(ak + (SM_ALO - SM_AHI), al[0], al[1], al[2], al[3]);
#pragma unroll
        for (int t = 0; t < 8; t++) {
            uint32_t bh0, bh1, bh2, bh3, bl0, bl1, bl2, bl3;
            uint32_t bk = boff + (uint32_t)t * (16 * PITCH * 2) + (uint32_t)k * 32;
            ldm_x4(bk, bh0, bh1, bh2, bh3);
            ldm_x4(bk + (SM_WLO - SM_WHI), bl0, bl1, bl2, bl3);
            mma_bf16(acc[2 * t + 0], ah, bh0, bh1);
            mma_bf16(acc[2 * t + 1], ah, bh2, bh3);
            mma_bf16(acc[2 * t + 0], al, bh0, bh1);
            mma_bf16(acc[2 * t + 1], al, bh2, bh3);
            mma_bf16(acc[2 * t + 0], ah, bl0, bl1);
            mma_bf16(acc[2 * t + 1], ah, bl2, bl3);
        }
    }

    // epilogue straight from fragments
    int grp = lane >> 2, qc = 2 * (lane & 3);
    size_t rA = row0 + warp * 16 + grp;
    size_t rB = rA + 8;
    float dA = dinv[rA]; dA *= dA;
    float dB = dinv[rB]; dB *= dB;
    float* Hr0 = H + rA * DD;
    float* Hr1 = H + rB * DD;
    float* Gr0 = AGG + rA * DD;
    float* Gr1 = AGG + rB * DD;
#pragma unroll
    for (int nt = 0; nt < 16; nt++) {
        int col = nt * 8 + qc;
        *(float2*)(Hr0 + col) = make_float2(acc[nt][0], acc[nt][1]);
        *(float2*)(Hr1 + col) = make_float2(acc[nt][2], acc[nt][3]);
        *(float2*)(Gr0 + col) = make_float2(acc[nt][0] * dA, acc[nt][1] * dA);
        *(float2*)(Gr1 + col) = make_float2(acc[nt][2] * dB, acc[nt][3] * dB);
    }
}

// ---------------- scatter / final ----------------
__global__ void scatter_kernel(const int* __restrict__ ui, const int* __restrict__ ii,
                               const float* __restrict__ H, const float* __restrict__ dinv,
                               float* __restrict__ AGG) {
    int t = blockIdx.x * blockDim.x + threadIdx.x;
    int e = t >> 5;
    if (e >= BB) return;
    int lane = t & 31;
    int a = ii[e];
    int b = ui[e] + BB;
    float norm = dinv[a] * dinv[b];
    float4 va = ((const float4*)(H + (size_t)b * DD))[lane];
    float4 vb = ((const float4*)(H + (size_t)a * DD))[lane];
    va.x *= norm; va.y *= norm; va.z *= norm; va.w *= norm;
    vb.x *= norm; vb.y *= norm; vb.z *= norm; vb.w *= norm;
    red_add4(AGG + (size_t)a * DD + lane * 4, va);
    red_add4(AGG + (size_t)b * DD + lane * 4, vb);
}

__global__ void final_kernel(const float* __restrict__ Z, const float* __restrict__ b,
                             float* __restrict__ out) {
    int idx = blockIdx.x * blockDim.x + threadIdx.x;
    if (idx >= NN * 32) return;
    int c = idx & 31;
    float4 v = ((const float4*)Z)[idx];
    float4 bb = ((const float4*)b)[c];
    v.x = fmaxf(v.x + bb.x, 0.0f);
    v.y = fmaxf(v.y + bb.y, 0.0f);
    v.z = fmaxf(v.z + bb.z, 0.0f);
    v.w = fmaxf(v.w + bb.w, 0.0f);
    ((float4*)out)[idx] = v;
}

extern "C" void kernel_launch(void* const* d_in, const int* in_sizes, int n_in,
                              void* d_out, int out_size) {
    const int*   ui   = (const int*)d_in[0];
    const int*   ii   = (const int*)d_in[1];
    const float* UT   = (const float*)d_in[2];
    const float* IT   = (const float*)d_in[3];
    const float* Wall = (const float*)d_in[4];
    const float* ball = (const float*)d_in[5];
    float* out = (float*)d_out;

    float *deg, *H, *P0, *P1;
    cudaGetSymbolAddress((void**)&deg, g_deg);
    cudaGetSymbolAddress((void**)&H,   g_H);
    cudaGetSymbolAddress((void**)&P0,  g_P0);
    cudaGetSymbolAddress((void**)&P1,  g_P1);

    cudaFuncSetAttribute(tc_gemm_kernel, cudaFuncAttributeMaxDynamicSharedMemorySize, SM_TOTAL);

    init_deg_kernel<<<(NN + 255) / 256, 256>>>();
    count_deg_kernel<<<(BB + 255) / 256, 256>>>(ui, ii);
    dinv_kernel<<<(NN + 255) / 256, 256>>>();
    wprep_kernel<<<(3 * 128 * 128 + 255) / 256, 256>>>(Wall);

    // layer 0: fused gather (X param = user table, bprev param = item table, no act)
    tc_gemm_kernel<<<NN / 128, 256, SM_TOTAL>>>(UT, ui, ii, 1, 0, IT, 0, deg, H, P0);
    scatter_kernel<<<(BB * 32 + 255) / 256, 256>>>(ui, ii, H, deg, P0);
    // layer 1: relu(P0 + b0)
    tc_gemm_kernel<<<NN / 128, 256, SM_TOTAL>>>(P0, ui, ii, 0, 1, ball, 1, deg, H, P1);
    scatter_kernel<<<(BB * 32 + 255) / 256, 256>>>(ui, ii, H, deg, P1);
    // layer 2: relu(P1 + b1)
    tc_gemm_kernel<<<NN / 128, 256, SM_TOTAL>>>(P1, ui, ii, 0, 2, ball + DD, 1, deg, H, P0);
    scatter_kernel<<<(BB * 32 + 255) / 256, 256>>>(ui, ii, H, deg, P0);

    final_kernel<<<(NN * 32 + 255) / 256, 256>>>(P0, ball + 2 * DD, out);
}